// round 4
// baseline (speedup 1.0000x reference)
#include <cuda_runtime.h>

#define NB 4096
#define NT 512
#define OBS 2
#define LAT 4
#define NH 20
#define RNNH 25

// output layout: pred_x (B,T,OBS) | z0 (B,LAT) | qz0_mean | qz0_logvar
#define OFF_Z0   (NB * NT * OBS)
#define OFF_MEAN (OFF_Z0 + NB * LAT)
#define OFF_LV   (OFF_MEAN + NB * LAT)

// scratch: latent trajectory (B, T, LAT)
__device__ float g_predz[NB * NT * LAT];

typedef unsigned long long u64;

// ---- packed f32x2 helpers (SASS FFMA2 path) -------------------------------
__device__ __forceinline__ u64 pack2(float lo, float hi) {
    u64 r; asm("mov.b64 %0, {%1,%2};" : "=l"(r) : "f"(lo), "f"(hi)); return r;
}
__device__ __forceinline__ u64 dup2(float x) { return pack2(x, x); }
__device__ __forceinline__ void unpack2(u64 p, float& lo, float& hi) {
    asm("mov.b64 {%0,%1}, %2;" : "=f"(lo), "=f"(hi) : "l"(p));
}
__device__ __forceinline__ u64 fma2(u64 a, u64 b, u64 c) {
    u64 d; asm("fma.rn.f32x2 %0, %1, %2, %3;" : "=l"(d) : "l"(a), "l"(b), "l"(c));
    return d;
}
__device__ __forceinline__ u64 add2(u64 a, u64 b) {
    u64 d; asm("add.rn.f32x2 %0, %1, %2;" : "=l"(d) : "l"(a), "l"(b)); return d;
}

__device__ __forceinline__ float elu_f(float x) {
    return fmaxf(x, 0.f) + (__expf(fminf(x, 0.f)) - 1.f);
}
__device__ __forceinline__ u64 elu2(u64 p) {
    float a, b; unpack2(p, a, b);
    return pack2(elu_f(a), elu_f(b));
}
__device__ __forceinline__ float fast_tanh(float x) {
    float a = fabsf(x);
    float e = __expf(-2.f * a);
    float r = __fdividef(1.f - e, 1.f + e);
    return copysignf(r, x);
}

// ---------------------------------------------------------------------------
// Kernel 1: backward RNN scan + encoder head + z0.
// One warp = TWO batches (packed f32x2). Lane j (<25) owns hidden unit j.
// x-stream prefetched one step ahead; recurrence uses 4 partial accumulators.
// ---------------------------------------------------------------------------
__global__ __launch_bounds__(256)
void rnn_kernel(const float* __restrict__ trajs,
                const float* __restrict__ eps,
                const float* __restrict__ i2h_w,
                const float* __restrict__ i2h_b,
                const float* __restrict__ h2o_w,
                const float* __restrict__ h2o_b,
                float* __restrict__ out)
{
    const int wIn  = threadIdx.x >> 5;
    const int lane = threadIdx.x & 31;
    const int gw   = blockIdx.x * 8 + wIn;
    const int b0   = 2 * gw;
    const int b1   = b0 + 1;

    __shared__ __align__(16) float2 hs[8][2][28];   // double-buffered packed h

    const int j = (lane < RNNH) ? lane : 0;
    u64 wx0 = dup2(i2h_w[j]);
    u64 wx1 = dup2(i2h_w[RNNH + j]);
    u64 wh[28];
#pragma unroll
    for (int i = 0; i < RNNH; ++i) wh[i] = dup2(i2h_w[(2 + i) * RNNH + j]);
#pragma unroll
    for (int i = RNNH; i < 28; ++i) wh[i] = 0ull;
    u64 bb = dup2(i2h_b[j]);

    if (lane < 28) {
        hs[wIn][0][lane] = make_float2(0.f, 0.f);
        hs[wIn][1][lane] = make_float2(0.f, 0.f);
    }
    __syncwarp();

    const float2* xrow0 = (const float2*)trajs + (size_t)b0 * NT;
    const float2* xrow1 = (const float2*)trajs + (size_t)b1 * NT;

    float2 nx0 = xrow0[NT - 1];
    float2 nx1 = xrow1[NT - 1];

    int cur = 0;
    for (int t = NT - 1; t >= 0; --t) {
        float2 x0 = nx0, x1 = nx1;
        if (t > 0) { nx0 = xrow0[t - 1]; nx1 = xrow1[t - 1]; }  // prefetch next step

        const ulonglong2* hb = (const ulonglong2*)hs[wIn][cur];
        // 4 partial accumulators over 28 packed units
        u64 a0 = fma2(pack2(x0.x, x1.x), wx0, bb);
        u64 a1 = fma2(pack2(x0.y, x1.y), wx1, 0ull);
        u64 a2 = 0ull, a3 = 0ull;
#pragma unroll
        for (int q = 0; q < 7; ++q) {
            ulonglong2 hva = hb[2 * q];
            ulonglong2 hvb = hb[2 * q + 1];
            a0 = fma2(hva.x, wh[4 * q + 0], a0);
            a1 = fma2(hva.y, wh[4 * q + 1], a1);
            a2 = fma2(hvb.x, wh[4 * q + 2], a2);
            a3 = fma2(hvb.y, wh[4 * q + 3], a3);
        }
        u64 acc = add2(add2(a0, a1), add2(a2, a3));
        float alo, ahi; unpack2(acc, alo, ahi);
        if (lane < RNNH)
            hs[wIn][cur ^ 1][lane] = make_float2(fast_tanh(alo), fast_tanh(ahi));
        __syncwarp();
        cur ^= 1;
    }

    // encoder head: out8 = h_last @ h2o_w + b  (lanes 0..7, packed 2 batches)
    u64 o = 0ull;
    if (lane < 8) {
        o = dup2(h2o_b[lane]);
        const float2* hl = hs[wIn][cur];
#pragma unroll
        for (int i = 0; i < RNNH; ++i) {
            float2 h = hl[i];
            o = fma2(pack2(h.x, h.y), dup2(h2o_w[i * 8 + lane]), o);
        }
    }
    u64 lv = __shfl_sync(0xffffffffu, o, lane + 4);
    if (lane < LAT) {
        float m0, m1, l0, l1;
        unpack2(o, m0, m1);
        unpack2(lv, l0, l1);
        float z00 = fmaf(eps[b0 * LAT + lane], expf(0.5f * l0), m0);
        float z01 = fmaf(eps[b1 * LAT + lane], expf(0.5f * l1), m1);
        out[OFF_MEAN + b0 * LAT + lane] = m0;
        out[OFF_MEAN + b1 * LAT + lane] = m1;
        out[OFF_Z0 + b0 * LAT + lane] = z00;
        out[OFF_Z0 + b1 * LAT + lane] = z01;
        g_predz[(size_t)b0 * NT * LAT + lane] = z00;
        g_predz[(size_t)b1 * NT * LAT + lane] = z01;
    }
    if (lane >= 4 && lane < 8) {
        float l0, l1; unpack2(o, l0, l1);
        out[OFF_LV + b0 * LAT + (lane - 4)] = l0;
        out[OFF_LV + b1 * LAT + (lane - 4)] = l1;
    }
}

// ---------------------------------------------------------------------------
// Kernel 2: RK4 ODE scan. One warp = TWO batches (packed f32x2).
// z kept register-resident, replicated in ALL lanes (k broadcast by shfl).
// Shared exchange only for u1/u2. 2 syncwarps per f-eval.
// ---------------------------------------------------------------------------
__global__ __launch_bounds__(256)
void ode_kernel(const float* __restrict__ ts,
                const float* __restrict__ f1_w, const float* __restrict__ f1_b,
                const float* __restrict__ f2_w, const float* __restrict__ f2_b,
                const float* __restrict__ f3_w, const float* __restrict__ f3_b)
{
    const int wIn  = threadIdx.x >> 5;
    const int lane = threadIdx.x & 31;
    const int gw   = blockIdx.x * 8 + wIn;
    const int b0   = 2 * gw;
    const int b1   = b0 + 1;

    __shared__ __align__(16) u64 sbuf[8 * 44];   // per warp: [0..19]=u1, [22..41]=u2
    __shared__ float s_dt[NT];

    for (int i = threadIdx.x; i < NT - 1; i += blockDim.x)
        s_dt[i] = ts[i + 1] - ts[i];
    __syncthreads();

    u64* swu1 = sbuf + wIn * 44;
    u64* swu2 = swu1 + 22;

    const int j = (lane < NH) ? lane : 0;
    u64 w1r[LAT];
#pragma unroll
    for (int i = 0; i < LAT; ++i) w1r[i] = dup2(f1_w[i * NH + j]);
    u64 b1r = dup2(f1_b[j]);
    u64 w2c[NH];
#pragma unroll
    for (int i = 0; i < NH; ++i) w2c[i] = dup2(f2_w[i * NH + j]);
    u64 b2r = dup2(f2_b[j]);

    // layer3: lanes 0..7; lane l computes output (l&3) over inputs [(l>>2)*10, +10)
    const int l4 = lane & 3;
    const int half = (lane >> 2) & 1;
    u64 w3c[10];
#pragma unroll
    for (int i = 0; i < 10; ++i) w3c[i] = dup2(f3_w[(half * 10 + i) * LAT + l4]);
    u64 b3r = (half == 0) ? dup2(f3_b[l4]) : 0ull;

    // z state replicated in every lane (uniform loads)
    const float* z0p0 = &g_predz[(size_t)b0 * NT * LAT];
    const float* z0p1 = &g_predz[(size_t)b1 * NT * LAT];
    u64 zc0 = pack2(z0p0[0], z0p1[0]);
    u64 zc1 = pack2(z0p0[1], z0p1[1]);
    u64 zc2 = pack2(z0p0[2], z0p1[2]);
    u64 zc3 = pack2(z0p0[3], z0p1[3]);
    u64 zi0 = zc0, zi1 = zc1, zi2 = zc2, zi3 = zc3;
    u64 ka0 = 0ull, ka1 = 0ull, ka2 = 0ull, ka3 = 0ull;

    const u64 two = dup2(2.f);

    for (int t = 0; t < NT - 1; ++t) {
        const float dt = s_dt[t];
        const u64 hdt = dup2(0.5f * dt);
        const u64 fdt = dup2(dt);
        const u64 sdt = dup2(dt * (1.f / 6.f));
#pragma unroll
        for (int e = 0; e < 4; ++e) {
            // layer1: z in registers, no LDS
            u64 a1 = fma2(zi0, w1r[0],
                     fma2(zi1, w1r[1],
                     fma2(zi2, w1r[2],
                     fma2(zi3, w1r[3], b1r))));
            a1 = elu2(a1);
            if (lane < NH) swu1[lane] = a1;
            __syncwarp();

            // layer2: 4 partial accumulators over 20 packed inputs
            u64 c0 = b2r, c1 = 0ull, c2 = 0ull, c3 = 0ull;
            const ulonglong2* u1v = (const ulonglong2*)swu1;
#pragma unroll
            for (int q = 0; q < 5; ++q) {
                ulonglong2 va = u1v[2 * q];
                ulonglong2 vb = u1v[2 * q + 1];
                c0 = fma2(va.x, w2c[4 * q + 0], c0);
                c1 = fma2(va.y, w2c[4 * q + 1], c1);
                c2 = fma2(vb.x, w2c[4 * q + 2], c2);
                c3 = fma2(vb.y, w2c[4 * q + 3], c3);
            }
            u64 u2 = elu2(add2(add2(c0, c1), add2(c2, c3)));
            if (lane < NH) swu2[lane] = u2;
            __syncwarp();

            // layer3 (lanes 0..7 meaningful): 2 partial chains of 5
            u64 p0 = b3r, p1 = 0ull;
            {
                const ulonglong2* u2v = (const ulonglong2*)(swu2 + half * 10);
#pragma unroll
                for (int q = 0; q < 5; ++q) {
                    ulonglong2 v = u2v[q];
                    p0 = fma2(v.x, w3c[2 * q + 0], p0);
                    p1 = fma2(v.y, w3c[2 * q + 1], p1);
                }
            }
            u64 kk = add2(p0, p1);
            kk = add2(kk, __shfl_down_sync(0xffffffffu, kk, 4));

            // broadcast k components to all lanes
            u64 k0 = __shfl_sync(0xffffffffu, kk, 0);
            u64 k1 = __shfl_sync(0xffffffffu, kk, 1);
            u64 k2 = __shfl_sync(0xffffffffu, kk, 2);
            u64 k3 = __shfl_sync(0xffffffffu, kk, 3);

            // redundant state update in every lane (no smem round-trip)
            if (e == 0) {
                ka0 = k0; ka1 = k1; ka2 = k2; ka3 = k3;
                zi0 = fma2(hdt, k0, zc0); zi1 = fma2(hdt, k1, zc1);
                zi2 = fma2(hdt, k2, zc2); zi3 = fma2(hdt, k3, zc3);
            } else if (e == 1) {
                ka0 = fma2(two, k0, ka0); ka1 = fma2(two, k1, ka1);
                ka2 = fma2(two, k2, ka2); ka3 = fma2(two, k3, ka3);
                zi0 = fma2(hdt, k0, zc0); zi1 = fma2(hdt, k1, zc1);
                zi2 = fma2(hdt, k2, zc2); zi3 = fma2(hdt, k3, zc3);
            } else if (e == 2) {
                ka0 = fma2(two, k0, ka0); ka1 = fma2(two, k1, ka1);
                ka2 = fma2(two, k2, ka2); ka3 = fma2(two, k3, ka3);
                zi0 = fma2(fdt, k0, zc0); zi1 = fma2(fdt, k1, zc1);
                zi2 = fma2(fdt, k2, zc2); zi3 = fma2(fdt, k3, zc3);
            } else {
                ka0 = add2(ka0, k0); ka1 = add2(ka1, k1);
                ka2 = add2(ka2, k2); ka3 = add2(ka3, k3);
                zc0 = fma2(sdt, ka0, zc0); zc1 = fma2(sdt, ka1, zc1);
                zc2 = fma2(sdt, ka2, zc2); zc3 = fma2(sdt, ka3, zc3);
                zi0 = zc0; zi1 = zc1; zi2 = zc2; zi3 = zc3;
            }
        }
        // store z_{t+1}: lane 0 -> batch b0 (lo), lane 1 -> batch b1 (hi)
        if (lane < 2) {
            float q0l, q0h, q1l, q1h, q2l, q2h, q3l, q3h;
            unpack2(zc0, q0l, q0h); unpack2(zc1, q1l, q1h);
            unpack2(zc2, q2l, q2h); unpack2(zc3, q3l, q3h);
            float4 v = (lane == 0) ? make_float4(q0l, q1l, q2l, q3l)
                                   : make_float4(q0h, q1h, q2h, q3h);
            const int bb = (lane == 0) ? b0 : b1;
            *(float4*)&g_predz[((size_t)bb * NT + t + 1) * LAT] = v;
        }
    }
}

// ---------------------------------------------------------------------------
// Kernel 3: decoder — fully parallel over (b, t).
// ---------------------------------------------------------------------------
__global__ __launch_bounds__(256)
void dec_kernel(const float* __restrict__ d1_w, const float* __restrict__ d1_b,
                const float* __restrict__ d2_w, const float* __restrict__ d2_b,
                float* __restrict__ out)
{
    __shared__ float sw1[LAT * NH], sb1[NH], sw2[NH * OBS], sb2[OBS];
    if (threadIdx.x < LAT * NH) sw1[threadIdx.x] = d1_w[threadIdx.x];
    if (threadIdx.x < NH)       sb1[threadIdx.x] = d1_b[threadIdx.x];
    if (threadIdx.x < NH * OBS) sw2[threadIdx.x] = d2_w[threadIdx.x];
    if (threadIdx.x < OBS)      sb2[threadIdx.x] = d2_b[threadIdx.x];
    __syncthreads();

    int idx = blockIdx.x * blockDim.x + threadIdx.x;   // < NB*NT
    float4 z = *(const float4*)&g_predz[(size_t)idx * LAT];

    float acc0 = sb2[0], acc1 = sb2[1];
#pragma unroll
    for (int jj = 0; jj < NH; ++jj) {
        float h = fmaf(z.x, sw1[0 * NH + jj],
                  fmaf(z.y, sw1[1 * NH + jj],
                  fmaf(z.z, sw1[2 * NH + jj],
                  fmaf(z.w, sw1[3 * NH + jj], sb1[jj]))));
        h = fmaxf(h, 0.f);
        acc0 = fmaf(h, sw2[jj * OBS + 0], acc0);
        acc1 = fmaf(h, sw2[jj * OBS + 1], acc1);
    }
    ((float2*)out)[idx] = make_float2(acc0, acc1);
}

// ---------------------------------------------------------------------------
extern "C" void kernel_launch(void* const* d_in, const int* in_sizes, int n_in,
                              void* d_out, int out_size)
{
    const float* samp_trajs = (const float*)d_in[0];
    const float* samp_ts    = (const float*)d_in[1];
    const float* epsilon    = (const float*)d_in[2];
    const float* i2h_w      = (const float*)d_in[3];
    const float* i2h_b      = (const float*)d_in[4];
    const float* h2o_w      = (const float*)d_in[5];
    const float* h2o_b      = (const float*)d_in[6];
    const float* f1_w       = (const float*)d_in[7];
    const float* f1_b       = (const float*)d_in[8];
    const float* f2_w       = (const float*)d_in[9];
    const float* f2_b       = (const float*)d_in[10];
    const float* f3_w       = (const float*)d_in[11];
    const float* f3_b       = (const float*)d_in[12];
    const float* d1_w       = (const float*)d_in[13];
    const float* d1_b       = (const float*)d_in[14];
    const float* d2_w       = (const float*)d_in[15];
    const float* d2_b       = (const float*)d_in[16];
    float* out = (float*)d_out;

    rnn_kernel<<<NB / 16, 256>>>(samp_trajs, epsilon, i2h_w, i2h_b, h2o_w, h2o_b, out);
    ode_kernel<<<NB / 16, 256>>>(samp_ts, f1_w, f1_b, f2_w, f2_b, f3_w, f3_b);
    dec_kernel<<<(NB * NT) / 256, 256>>>(d1_w, d1_b, d2_w, d2_b, out);
}